// round 6
// baseline (speedup 1.0000x reference)
#include <cuda_runtime.h>
#include <math.h>

#define B 8
#define N 256
#define D 128
#define H 256
#define BN (B * N)   // 2048

typedef unsigned long long ull;

// Scratch (allocation-free rule: device globals), 16B aligned for f32x2/ull access
__device__ __align__(16) float g_hi[BN * H];   // slots @ W_m1[:D]
__device__ __align__(16) float g_hj[BN * H];   // slots @ W_m1[D:] + b_m1
__device__ __align__(16) float g_G [BN * H];   // sum_j a_ij * gelu(hi_i + hj_j)

__device__ __forceinline__ float gelu_exact(float x) {
    return 0.5f * x * (1.0f + erff(x * 0.70710678118654752440f));
}

__device__ __forceinline__ ull pack2(float f) {
    unsigned int u = __float_as_uint(f);
    return (ull)u * 0x100000001ULL;     // u | (u << 32)
}

#define F2ADD(d,a,b)   asm("add.rn.f32x2 %0,%1,%2;"    : "=l"(d) : "l"(a), "l"(b))
#define F2MUL(d,a,b)   asm("mul.rn.f32x2 %0,%1,%2;"    : "=l"(d) : "l"(a), "l"(b))
#define F2FMA(d,a,b,c) asm("fma.rn.f32x2 %0,%1,%2,%3;" : "=l"(d) : "l"(a), "l"(b), "l"(c))

// ---------------------------------------------------------------------------
// Kernel 1: proj as a 2D-register-blocked smem GEMM, K-chunked (KC=32) to fit
// the 48KB static smem limit. Combined output [hi|hj] is (BN) x 512.
// Tile: 128 rows x 64 cols. Grid (16 row-blocks, 8 col-blocks), 256 threads.
// Thread owns 8 rows x 4 cols = 32 accumulators, 4096 FMA.
// ---------------------------------------------------------------------------
#define KC 32
__global__ __launch_bounds__(256) void proj_kernel(
    const float* __restrict__ slots, const float* __restrict__ W_m1,
    const float* __restrict__ b_m1)
{
    const int r0   = blockIdx.x * 128;       // row-block base (b*N + n)
    const int part = blockIdx.y >> 2;        // 0 -> hi, 1 -> hj
    const int c0   = (blockIdx.y & 3) * 64;  // column base within 256-wide half
    const int tid  = threadIdx.x;
    const int ty   = tid >> 4, tx = tid & 15;

    __shared__ float As[128][KC + 1];        // 16.5KB, pad -> conflict-free col reads
    __shared__ float Ws[KC][65];             // 8.3KB

    float acc[8][4];
#pragma unroll
    for (int r = 0; r < 8; ++r)
#pragma unroll
        for (int c = 0; c < 4; ++c) acc[r][c] = 0.f;

    const float* wsrc = W_m1 + (size_t)(part * D) * H + c0;

    for (int kc = 0; kc < D; kc += KC) {
        // load A chunk: 128 x 32 (each thread 16 elems, coalesced 32-wide rows)
#pragma unroll
        for (int l = 0; l < 16; ++l) {
            const int idx = tid + l * 256;           // 0..4095
            const int r = idx >> 5, k = idx & 31;
            As[r][k] = slots[(r0 + r) * D + kc + k];
        }
        // load W chunk: 32 x 64 (each thread 8 elems, coalesced 64-wide rows)
#pragma unroll
        for (int l = 0; l < 8; ++l) {
            const int idx = tid + l * 256;           // 0..2047
            const int k = idx >> 6, c = idx & 63;
            Ws[k][c] = wsrc[(kc + k) * H + c];
        }
        __syncthreads();

#pragma unroll
        for (int k = 0; k < KC; ++k) {
            float wv[4], av[8];
#pragma unroll
            for (int c = 0; c < 4; ++c) wv[c] = Ws[k][tx + 16 * c];
#pragma unroll
            for (int r = 0; r < 8; ++r) av[r] = As[ty + 16 * r][k];
#pragma unroll
            for (int r = 0; r < 8; ++r)
#pragma unroll
                for (int c = 0; c < 4; ++c)
                    acc[r][c] = fmaf(av[r], wv[c], acc[r][c]);
        }
        __syncthreads();
    }

    if (part == 0) {
#pragma unroll
        for (int r = 0; r < 8; ++r)
#pragma unroll
            for (int c = 0; c < 4; ++c)
                g_hi[(size_t)(r0 + ty + 16 * r) * H + c0 + tx + 16 * c] = acc[r][c];
    } else {
        float bm[4];
#pragma unroll
        for (int c = 0; c < 4; ++c) bm[c] = b_m1[c0 + tx + 16 * c];
#pragma unroll
        for (int r = 0; r < 8; ++r)
#pragma unroll
            for (int c = 0; c < 4; ++c)
                g_hj[(size_t)(r0 + ty + 16 * r) * H + c0 + tx + 16 * c] = acc[r][c] + bm[c];
    }
}

// ---------------------------------------------------------------------------
// Kernel 2 (dominant): G[b,i,h] = sum_j a[b,i,j] * gelu(hi[b,i,h] + hjp[b,j,h])
// 4 i-rows per block (grid 512), 256 threads: half-block hb = tid>>7 owns
// row-pair (2hb, 2hb+1); thread owns h-pair hp = tid&127 (packed f32x2).
// Both half-blocks load identical hj addresses -> L1/MSHR dedup; hj L2
// traffic halves vs 2-row blocks.
// gelu via branchless A&S 7.1.28 (max abs err 3e-7):
//   z = |x|/sqrt2; P = 1 + b1 z + ... + b6 z^6; erf = 1 - P^-16
//   gelu(x) = 0.5*((x+|x|) - |x| * P^-16)
// ---------------------------------------------------------------------------
__global__ __launch_bounds__(256) void msg_agg_kernel(
    const float* __restrict__ adj)
{
    const int row0 = blockIdx.x * 4;        // global row = b*N + i
    const int b    = row0 >> 8;
    const int i0   = row0 & (N - 1);
    const int tid  = threadIdx.x;
    const int hp   = tid & 127;             // h-pair = (2*hp, 2*hp+1)
    const int hb   = tid >> 7;              // 0/1 -> rows (2hb, 2hb+1)

    __shared__ ull a2_s[4][N];              // packed {0.5a, 0.5a}
    const float* adj_b = adj + ((size_t)b * N + i0) * N;
#pragma unroll
    for (int idx = tid; idx < 4 * N; idx += 256) {
        const float av = 0.5f * adj_b[idx];
        ((ull*)a2_s)[idx] = pack2(av);
    }
    __syncthreads();

    const ull ABSM = 0x7fffffff7fffffffULL;
    const ull SGNM = 0x8000000080000000ULL;
    const ull cis2 = pack2(0.70710678118654752440f);
    const ull cone = pack2(1.0f);
    const ull cb1  = pack2(0.0705230784f);
    const ull cb2  = pack2(0.0422820123f);
    const ull cb3  = pack2(0.0092705272f);
    const ull cb4  = pack2(0.0001520143f);
    const ull cb5  = pack2(0.0002765672f);
    const ull cb6  = pack2(0.0000430638f);

    const int ra = row0 + 2 * hb;           // this half-block's rows: ra, ra+1
    const ull* hj2 = (const ull*)(g_hj + (size_t)b * N * H) + hp;
    ull hi2[2];
    hi2[0] = ((const ull*)(g_hi + (size_t) ra      * H))[hp];
    hi2[1] = ((const ull*)(g_hi + (size_t)(ra + 1) * H))[hp];

    ull acc[2] = {0ULL, 0ULL};              // packed {0.f,0.f}

#pragma unroll 8
    for (int j = 0; j < N; ++j) {
        const ull hjv = hj2[(size_t)j * (H / 2)];
#pragma unroll
        for (int r = 0; r < 2; ++r) {
            ull x; F2ADD(x, hi2[r], hjv);
            const ull ax = x & ABSM;
            ull z; F2MUL(z, ax, cis2);
            ull p;
            F2FMA(p, cb6, z, cb5);
            F2FMA(p, p, z, cb4);
            F2FMA(p, p, z, cb3);
            F2FMA(p, p, z, cb2);
            F2FMA(p, p, z, cb1);
            F2FMA(p, p, z, cone);           // P
            F2MUL(p, p, p);                 // P^2
            F2MUL(p, p, p);                 // P^4
            F2MUL(p, p, p);                 // P^8
            F2MUL(p, p, p);                 // P^16
            float plo, phi, rlo, rhi;
            asm("mov.b64 {%0,%1},%2;" : "=f"(plo), "=f"(phi) : "l"(p));
            asm("rcp.approx.f32 %0,%1;" : "=f"(rlo) : "f"(plo));
            asm("rcp.approx.f32 %0,%1;" : "=f"(rhi) : "f"(phi));
            ull rr; asm("mov.b64 %0,{%1,%2};" : "=l"(rr) : "f"(rlo), "f"(rhi));
            ull u; F2ADD(u, x, ax);         // x + |x|
            const ull nax = ax ^ SGNM;      // -|x|
            ull g2; F2FMA(g2, nax, rr, u);  // 2*gelu(x)
            F2FMA(acc[r], a2_s[2 * hb + r][j], g2, acc[r]);
        }
    }

    ((ull*)(g_G + (size_t) ra      * H))[hp] = acc[0];
    ((ull*)(g_G + (size_t)(ra + 1) * H))[hp] = acc[1];
}

// ---------------------------------------------------------------------------
// Kernel 3: fused epilogue. 8 rows per block, 512 threads (grid 256).
//   agg = G @ W_m2 + rowsum(a)*b_m2
//   u   = slots@W_u1[:D] + agg@W_u1[D:] + b_u1 ; LayerNorm ; gelu
//   out = slots + u @ W_u2 + b_u2
// ---------------------------------------------------------------------------
__global__ __launch_bounds__(512) void epilogue_kernel(
    const float* __restrict__ slots, const float* __restrict__ adj,
    const float* __restrict__ W_m2, const float* __restrict__ b_m2,
    const float* __restrict__ W_u1, const float* __restrict__ b_u1,
    const float* __restrict__ ln_g, const float* __restrict__ ln_b,
    const float* __restrict__ W_u2, const float* __restrict__ b_u2,
    float* __restrict__ out)
{
    const int R  = 8;
    const int r0 = blockIdx.x * R;          // global row = b*N + n
    const int b  = r0 >> 8;
    const int n0 = r0 & (N - 1);
    const int tid = threadIdx.x;
    const int warp = tid >> 5, lane = tid & 31;

    __shared__ float buf_s[R][H];           // G tile, later reused as u tile
    __shared__ float s_s [R][D];
    __shared__ float agg_s[R][D];
    __shared__ float asum_s[R];
    __shared__ float mu_s[R], rstd_s[R];

    for (int idx = tid; idx < R * H; idx += 512)
        ((float*)buf_s)[idx] = g_G[r0 * H + idx];
    for (int idx = tid; idx < R * D; idx += 512)
        ((float*)s_s)[idx] = slots[r0 * D + idx];

    // adjacency row sums: warps 0..7 handle rows 0..7
    if (warp < R) {
        const float* arow = adj + ((size_t)b * N + n0 + warp) * N;
        float s = 0.f;
#pragma unroll
        for (int k = 0; k < 8; ++k) s += arow[lane + k * 32];
#pragma unroll
        for (int o = 16; o > 0; o >>= 1) s += __shfl_xor_sync(~0u, s, o);
        if (lane == 0) asum_s[warp] = s;
    }
    __syncthreads();

    // aggregated = G @ W_m2 + asum * b_m2
    {
        const int d  = tid & (D - 1);
        const int rb = (tid >> 7) * 2;       // rows rb, rb+1
        float acc[2];
        const float bm2 = b_m2[d];
#pragma unroll
        for (int r = 0; r < 2; ++r) acc[r] = asum_s[rb + r] * bm2;
#pragma unroll 8
        for (int hh = 0; hh < H; ++hh) {
            const float w = W_m2[hh * D + d];
#pragma unroll
            for (int r = 0; r < 2; ++r)
                acc[r] = fmaf(buf_s[rb + r][hh], w, acc[r]);
        }
        __syncthreads();                     // all reads of buf_s-as-G done
#pragma unroll
        for (int r = 0; r < 2; ++r) agg_s[rb + r][d] = acc[r];
    }
    __syncthreads();

    // u = slots@W_u1[:D] + agg@W_u1[D:] + b_u1   (overwrite buf_s)
    {
        const int h  = tid & 255;
        const int g  = tid >> 8;             // 0,1 -> rows 4g..4g+3
        float acc[4];
        const float bu = b_u1[h];
#pragma unroll
        for (int r = 0; r < 4; ++r) acc[r] = bu;
#pragma unroll 8
        for (int d = 0; d < D; ++d) {
            const float w1 = W_u1[d * H + h];
            const float w2 = W_u1[(D + d) * H + h];
#pragma unroll
            for (int r = 0; r < 4; ++r) {
                acc[r] = fmaf(s_s[4 * g + r][d], w1, acc[r]);
                acc[r] = fmaf(agg_s[4 * g + r][d], w2, acc[r]);
            }
        }
#pragma unroll
        for (int r = 0; r < 4; ++r) buf_s[4 * g + r][h] = acc[r];
    }
    __syncthreads();

    // LayerNorm stats: warps 0..7, one row each (two-pass)
    if (warp < R) {
        const int r = warp;
        float s = 0.f;
#pragma unroll
        for (int k = 0; k < 8; ++k) s += buf_s[r][lane + k * 32];
#pragma unroll
        for (int o = 16; o > 0; o >>= 1) s += __shfl_xor_sync(~0u, s, o);
        const float mu = s * (1.f / H);
        float ss = 0.f;
#pragma unroll
        for (int k = 0; k < 8; ++k) {
            const float v = buf_s[r][lane + k * 32] - mu;
            ss += v * v;
        }
#pragma unroll
        for (int o = 16; o > 0; o >>= 1) ss += __shfl_xor_sync(~0u, ss, o);
        if (lane == 0) {
            mu_s[r]   = mu;
            rstd_s[r] = rsqrtf(ss * (1.f / H) + 1e-5f);
        }
    }
    __syncthreads();

    // normalize + gelu (in place)
    {
        const int h = tid & 255;
        const int g = tid >> 8;
        const float gg = ln_g[h], bb = ln_b[h];
#pragma unroll
        for (int r = 0; r < 4; ++r) {
            const int rr = 4 * g + r;
            const float v = (buf_s[rr][h] - mu_s[rr]) * rstd_s[rr] * gg + bb;
            buf_s[rr][h] = gelu_exact(v);
        }
    }
    __syncthreads();

    // out = slots + u @ W_u2 + b_u2
    {
        const int d  = tid & (D - 1);
        const int rb = (tid >> 7) * 2;
        float acc[2];
        const float bu2 = b_u2[d];
#pragma unroll
        for (int r = 0; r < 2; ++r) acc[r] = bu2;
#pragma unroll 8
        for (int hh = 0; hh < H; ++hh) {
            const float w = W_u2[hh * D + d];
#pragma unroll
            for (int r = 0; r < 2; ++r)
                acc[r] = fmaf(buf_s[rb + r][hh], w, acc[r]);
        }
#pragma unroll
        for (int r = 0; r < 2; ++r)
            out[(r0 + rb + r) * D + d] = s_s[rb + r][d] + acc[r];
    }
}

// ---------------------------------------------------------------------------
extern "C" void kernel_launch(void* const* d_in, const int* in_sizes, int n_in,
                              void* d_out, int out_size)
{
    const float* slots = (const float*)d_in[0];
    const float* adj   = (const float*)d_in[1];
    const float* W_m1  = (const float*)d_in[2];
    const float* b_m1  = (const float*)d_in[3];
    const float* W_m2  = (const float*)d_in[4];
    const float* b_m2  = (const float*)d_in[5];
    const float* W_u1  = (const float*)d_in[6];
    const float* b_u1  = (const float*)d_in[7];
    const float* ln_g  = (const float*)d_in[8];
    const float* ln_b  = (const float*)d_in[9];
    const float* W_u2  = (const float*)d_in[10];
    const float* b_u2  = (const float*)d_in[11];
    float* out = (float*)d_out;

    dim3 pg(BN / 128, 8);
    proj_kernel<<<pg, 256>>>(slots, W_m1, b_m1);
    msg_agg_kernel<<<BN / 4, 256>>>(adj);
    epilogue_kernel<<<BN / 8, 512>>>(slots, adj, W_m2, b_m2, W_u1, b_u1,
                                     ln_g, ln_b, W_u2, b_u2, out);
}

// round 7
// speedup vs baseline: 1.0925x; 1.0925x over previous
#include <cuda_runtime.h>
#include <math.h>

#define B 8
#define N 256
#define D 128
#define H 256
#define BN (B * N)   // 2048

typedef unsigned long long ull;

// Scratch (allocation-free rule: device globals), 16B aligned for f32x2/ull access
__device__ __align__(16) float g_hi[BN * H];   // slots @ W_m1[:D]
__device__ __align__(16) float g_hj[BN * H];   // slots @ W_m1[D:] + b_m1
__device__ __align__(16) float g_G [BN * H];   // sum_j a_ij * gelu(hi_i + hj_j)

__device__ __forceinline__ float gelu_exact(float x) {
    return 0.5f * x * (1.0f + erff(x * 0.70710678118654752440f));
}

__device__ __forceinline__ ull pack2(float f) {
    unsigned int u = __float_as_uint(f);
    return (ull)u * 0x100000001ULL;     // u | (u << 32)
}

#define F2ADD(d,a,b)   asm("add.rn.f32x2 %0,%1,%2;"    : "=l"(d) : "l"(a), "l"(b))
#define F2MUL(d,a,b)   asm("mul.rn.f32x2 %0,%1,%2;"    : "=l"(d) : "l"(a), "l"(b))
#define F2FMA(d,a,b,c) asm("fma.rn.f32x2 %0,%1,%2,%3;" : "=l"(d) : "l"(a), "l"(b), "l"(c))

// ---------------------------------------------------------------------------
// Kernel 1: proj as a 2D-register-blocked smem GEMM, K-chunked (KC=32) to fit
// the 48KB static smem limit. Combined output [hi|hj] is (BN) x 512.
// Tile: 128 rows x 64 cols. Grid (16 row-blocks, 8 col-blocks), 256 threads.
// ---------------------------------------------------------------------------
#define KC 32
__global__ __launch_bounds__(256) void proj_kernel(
    const float* __restrict__ slots, const float* __restrict__ W_m1,
    const float* __restrict__ b_m1)
{
    const int r0   = blockIdx.x * 128;       // row-block base (b*N + n)
    const int part = blockIdx.y >> 2;        // 0 -> hi, 1 -> hj
    const int c0   = (blockIdx.y & 3) * 64;  // column base within 256-wide half
    const int tid  = threadIdx.x;
    const int ty   = tid >> 4, tx = tid & 15;

    __shared__ float As[128][KC + 1];        // pad -> conflict-free col reads
    __shared__ float Ws[KC][65];

    float acc[8][4];
#pragma unroll
    for (int r = 0; r < 8; ++r)
#pragma unroll
        for (int c = 0; c < 4; ++c) acc[r][c] = 0.f;

    const float* wsrc = W_m1 + (size_t)(part * D) * H + c0;

    for (int kc = 0; kc < D; kc += KC) {
#pragma unroll
        for (int l = 0; l < 16; ++l) {
            const int idx = tid + l * 256;           // 0..4095
            const int r = idx >> 5, k = idx & 31;
            As[r][k] = slots[(r0 + r) * D + kc + k];
        }
#pragma unroll
        for (int l = 0; l < 8; ++l) {
            const int idx = tid + l * 256;           // 0..2047
            const int k = idx >> 6, c = idx & 63;
            Ws[k][c] = wsrc[(kc + k) * H + c];
        }
        __syncthreads();

#pragma unroll
        for (int k = 0; k < KC; ++k) {
            float wv[4], av[8];
#pragma unroll
            for (int c = 0; c < 4; ++c) wv[c] = Ws[k][tx + 16 * c];
#pragma unroll
            for (int r = 0; r < 8; ++r) av[r] = As[ty + 16 * r][k];
#pragma unroll
            for (int r = 0; r < 8; ++r)
#pragma unroll
                for (int c = 0; c < 4; ++c)
                    acc[r][c] = fmaf(av[r], wv[c], acc[r][c]);
        }
        __syncthreads();
    }

    if (part == 0) {
#pragma unroll
        for (int r = 0; r < 8; ++r)
#pragma unroll
            for (int c = 0; c < 4; ++c)
                g_hi[(size_t)(r0 + ty + 16 * r) * H + c0 + tx + 16 * c] = acc[r][c];
    } else {
        float bm[4];
#pragma unroll
        for (int c = 0; c < 4; ++c) bm[c] = b_m1[c0 + tx + 16 * c];
#pragma unroll
        for (int r = 0; r < 8; ++r)
#pragma unroll
            for (int c = 0; c < 4; ++c)
                g_hj[(size_t)(r0 + ty + 16 * r) * H + c0 + tx + 16 * c] = acc[r][c] + bm[c];
    }
}

// ---------------------------------------------------------------------------
// Kernel 2 (dominant): G[b,i,h] = sum_j a[b,i,j] * gelu(hi[b,i,h] + hjp[b,j,h])
// R4-proven shape: 2 i-rows per block (grid 1024), 128 threads, thread owns
// an h-pair (packed f32x2).
// gelu via branchless A&S 7.1.28 (max abs err 3e-7), with the 1/sqrt2 scale
// folded into the coefficients (poly evaluated directly in |x|):
//   P = 1 + b1' |x| + ... + b6' |x|^6,  b_k' = b_k * 2^(-k/2)
//   gelu(x) = 0.5*((x+|x|) - |x| * P^-16)
// ---------------------------------------------------------------------------
__global__ __launch_bounds__(128) void msg_agg_kernel(
    const float* __restrict__ adj)
{
    const int row0 = blockIdx.x * 2;        // global row = b*N + i
    const int b    = row0 >> 8;
    const int i0   = row0 & (N - 1);
    const int tid  = threadIdx.x;           // h-pair = (2*tid, 2*tid+1)

    __shared__ ull a2_s[2][N];              // packed {0.5a, 0.5a}
    const float* adj_b = adj + ((size_t)b * N + i0) * N;
#pragma unroll
    for (int idx = tid; idx < 2 * N; idx += 128) {
        const float av = 0.5f * adj_b[idx];
        ((ull*)a2_s)[idx] = pack2(av);
    }
    __syncthreads();

    const ull ABSM = 0x7fffffff7fffffffULL;
    const ull SGNM = 0x8000000080000000ULL;
    const ull cone = pack2(1.0f);
    const ull cb1  = pack2(4.98677908e-2f);  // b1 * 2^-1/2
    const ull cb2  = pack2(2.11410062e-2f);  // b2 * 2^-1
    const ull cb3  = pack2(3.27762714e-3f);  // b3 * 2^-3/2
    const ull cb4  = pack2(3.80035750e-5f);  // b4 * 2^-2
    const ull cb5  = pack2(4.88897213e-5f);  // b5 * 2^-5/2
    const ull cb6  = pack2(5.38297500e-6f);  // b6 * 2^-3

    const ull* hj2 = (const ull*)(g_hj + (size_t)b * N * H) + tid;
    ull hi2[2];
    hi2[0] = ((const ull*)(g_hi + (size_t) row0      * H))[tid];
    hi2[1] = ((const ull*)(g_hi + (size_t)(row0 + 1) * H))[tid];

    ull acc[2] = {0ULL, 0ULL};              // packed {0.f,0.f}

#pragma unroll 8
    for (int j = 0; j < N; ++j) {
        const ull hjv = hj2[(size_t)j * (H / 2)];
#pragma unroll
        for (int r = 0; r < 2; ++r) {
            ull x; F2ADD(x, hi2[r], hjv);
            const ull ax = x & ABSM;
            ull p;
            F2FMA(p, cb6, ax, cb5);
            F2FMA(p, p, ax, cb4);
            F2FMA(p, p, ax, cb3);
            F2FMA(p, p, ax, cb2);
            F2FMA(p, p, ax, cb1);
            F2FMA(p, p, ax, cone);          // P
            F2MUL(p, p, p);                 // P^2
            F2MUL(p, p, p);                 // P^4
            F2MUL(p, p, p);                 // P^8
            F2MUL(p, p, p);                 // P^16
            float plo, phi, rlo, rhi;
            asm("mov.b64 {%0,%1},%2;" : "=f"(plo), "=f"(phi) : "l"(p));
            asm("rcp.approx.f32 %0,%1;" : "=f"(rlo) : "f"(plo));
            asm("rcp.approx.f32 %0,%1;" : "=f"(rhi) : "f"(phi));
            ull rr; asm("mov.b64 %0,{%1,%2};" : "=l"(rr) : "f"(rlo), "f"(rhi));
            ull u; F2ADD(u, x, ax);         // x + |x|
            const ull nax = ax ^ SGNM;      // -|x|
            ull g2; F2FMA(g2, nax, rr, u);  // 2*gelu(x)
            F2FMA(acc[r], a2_s[r][j], g2, acc[r]);
        }
    }

    ((ull*)(g_G + (size_t) row0      * H))[tid] = acc[0];
    ((ull*)(g_G + (size_t)(row0 + 1) * H))[tid] = acc[1];
}

// ---------------------------------------------------------------------------
// Kernel 3: fused epilogue. 8 rows per block, 512 threads (grid 256).
//   agg = G @ W_m2 + rowsum(a)*b_m2
//   u   = slots@W_u1[:D] + agg@W_u1[D:] + b_u1 ; LayerNorm ; gelu
//   out = slots + u @ W_u2 + b_u2
// ---------------------------------------------------------------------------
__global__ __launch_bounds__(512) void epilogue_kernel(
    const float* __restrict__ slots, const float* __restrict__ adj,
    const float* __restrict__ W_m2, const float* __restrict__ b_m2,
    const float* __restrict__ W_u1, const float* __restrict__ b_u1,
    const float* __restrict__ ln_g, const float* __restrict__ ln_b,
    const float* __restrict__ W_u2, const float* __restrict__ b_u2,
    float* __restrict__ out)
{
    const int R  = 8;
    const int r0 = blockIdx.x * R;          // global row = b*N + n
    const int b  = r0 >> 8;
    const int n0 = r0 & (N - 1);
    const int tid = threadIdx.x;
    const int warp = tid >> 5, lane = tid & 31;

    __shared__ float buf_s[R][H];           // G tile, later reused as u tile
    __shared__ float s_s [R][D];
    __shared__ float agg_s[R][D];
    __shared__ float asum_s[R];
    __shared__ float mu_s[R], rstd_s[R];

    for (int idx = tid; idx < R * H; idx += 512)
        ((float*)buf_s)[idx] = g_G[r0 * H + idx];
    for (int idx = tid; idx < R * D; idx += 512)
        ((float*)s_s)[idx] = slots[r0 * D + idx];

    // adjacency row sums: warps 0..7 handle rows 0..7
    if (warp < R) {
        const float* arow = adj + ((size_t)b * N + n0 + warp) * N;
        float s = 0.f;
#pragma unroll
        for (int k = 0; k < 8; ++k) s += arow[lane + k * 32];
#pragma unroll
        for (int o = 16; o > 0; o >>= 1) s += __shfl_xor_sync(~0u, s, o);
        if (lane == 0) asum_s[warp] = s;
    }
    __syncthreads();

    // aggregated = G @ W_m2 + asum * b_m2
    {
        const int d  = tid & (D - 1);
        const int rb = (tid >> 7) * 2;       // rows rb, rb+1
        float acc[2];
        const float bm2 = b_m2[d];
#pragma unroll
        for (int r = 0; r < 2; ++r) acc[r] = asum_s[rb + r] * bm2;
#pragma unroll 8
        for (int hh = 0; hh < H; ++hh) {
            const float w = W_m2[hh * D + d];
#pragma unroll
            for (int r = 0; r < 2; ++r)
                acc[r] = fmaf(buf_s[rb + r][hh], w, acc[r]);
        }
        __syncthreads();                     // all reads of buf_s-as-G done
#pragma unroll
        for (int r = 0; r < 2; ++r) agg_s[rb + r][d] = acc[r];
    }
    __syncthreads();

    // u = slots@W_u1[:D] + agg@W_u1[D:] + b_u1   (overwrite buf_s)
    {
        const int h  = tid & 255;
        const int g  = tid >> 8;             // 0,1 -> rows 4g..4g+3
        float acc[4];
        const float bu = b_u1[h];
#pragma unroll
        for (int r = 0; r < 4; ++r) acc[r] = bu;
#pragma unroll 8
        for (int d = 0; d < D; ++d) {
            const float w1 = W_u1[d * H + h];
            const float w2 = W_u1[(D + d) * H + h];
#pragma unroll
            for (int r = 0; r < 4; ++r) {
                acc[r] = fmaf(s_s[4 * g + r][d], w1, acc[r]);
                acc[r] = fmaf(agg_s[4 * g + r][d], w2, acc[r]);
            }
        }
#pragma unroll
        for (int r = 0; r < 4; ++r) buf_s[4 * g + r][h] = acc[r];
    }
    __syncthreads();

    // LayerNorm stats: warps 0..7, one row each (two-pass)
    if (warp < R) {
        const int r = warp;
        float s = 0.f;
#pragma unroll
        for (int k = 0; k < 8; ++k) s += buf_s[r][lane + k * 32];
#pragma unroll
        for (int o = 16; o > 0; o >>= 1) s += __shfl_xor_sync(~0u, s, o);
        const float mu = s * (1.f / H);
        float ss = 0.f;
#pragma unroll
        for (int k = 0; k < 8; ++k) {
            const float v = buf_s[r][lane + k * 32] - mu;
            ss += v * v;
        }
#pragma unroll
        for (int o = 16; o > 0; o >>= 1) ss += __shfl_xor_sync(~0u, ss, o);
        if (lane == 0) {
            mu_s[r]   = mu;
            rstd_s[r] = rsqrtf(ss * (1.f / H) + 1e-5f);
        }
    }
    __syncthreads();

    // normalize + gelu (in place)
    {
        const int h = tid & 255;
        const int g = tid >> 8;
        const float gg = ln_g[h], bb = ln_b[h];
#pragma unroll
        for (int r = 0; r < 4; ++r) {
            const int rr = 4 * g + r;
            const float v = (buf_s[rr][h] - mu_s[rr]) * rstd_s[rr] * gg + bb;
            buf_s[rr][h] = gelu_exact(v);
        }
    }
    __syncthreads();

    // out = slots + u @ W_u2 + b_u2
    {
        const int d  = tid & (D - 1);
        const int rb = (tid >> 7) * 2;
        float acc[2];
        const float bu2 = b_u2[d];
#pragma unroll
        for (int r = 0; r < 2; ++r) acc[r] = bu2;
#pragma unroll 8
        for (int hh = 0; hh < H; ++hh) {
            const float w = W_u2[hh * D + d];
#pragma unroll
            for (int r = 0; r < 2; ++r)
                acc[r] = fmaf(buf_s[rb + r][hh], w, acc[r]);
        }
#pragma unroll
        for (int r = 0; r < 2; ++r)
            out[(r0 + rb + r) * D + d] = s_s[rb + r][d] + acc[r];
    }
}

// ---------------------------------------------------------------------------
extern "C" void kernel_launch(void* const* d_in, const int* in_sizes, int n_in,
                              void* d_out, int out_size)
{
    const float* slots = (const float*)d_in[0];
    const float* adj   = (const float*)d_in[1];
    const float* W_m1  = (const float*)d_in[2];
    const float* b_m1  = (const float*)d_in[3];
    const float* W_m2  = (const float*)d_in[4];
    const float* b_m2  = (const float*)d_in[5];
    const float* W_u1  = (const float*)d_in[6];
    const float* b_u1  = (const float*)d_in[7];
    const float* ln_g  = (const float*)d_in[8];
    const float* ln_b  = (const float*)d_in[9];
    const float* W_u2  = (const float*)d_in[10];
    const float* b_u2  = (const float*)d_in[11];
    float* out = (float*)d_out;

    dim3 pg(BN / 128, 8);
    proj_kernel<<<pg, 256>>>(slots, W_m1, b_m1);
    msg_agg_kernel<<<BN / 2, 128>>>(adj);
    epilogue_kernel<<<BN / 8, 512>>>(slots, adj, W_m2, b_m2, W_u1, b_u1,
                                     ln_g, ln_b, W_u2, b_u2, out);
}

// round 8
// speedup vs baseline: 1.0946x; 1.0019x over previous
#include <cuda_runtime.h>
#include <math.h>

#define B 8
#define N 256
#define D 128
#define H 256
#define BN (B * N)   // 2048

typedef unsigned long long ull;

// Scratch (allocation-free rule: device globals), 16B aligned for f32x2/ull access
__device__ __align__(16) float g_hi[BN * H];   // slots @ W_m1[:D]
__device__ __align__(16) float g_hj[BN * H];   // slots @ W_m1[D:] + b_m1
__device__ __align__(16) float g_G [BN * H];   // sum_j a_ij * gelu(hi_i + hj_j)

__device__ __forceinline__ float gelu_exact(float x) {
    return 0.5f * x * (1.0f + erff(x * 0.70710678118654752440f));
}

__device__ __forceinline__ ull pack2(float f) {
    unsigned int u = __float_as_uint(f);
    return (ull)u * 0x100000001ULL;     // u | (u << 32)
}

#define F2ADD(d,a,b)   asm("add.rn.f32x2 %0,%1,%2;"    : "=l"(d) : "l"(a), "l"(b))
#define F2MUL(d,a,b)   asm("mul.rn.f32x2 %0,%1,%2;"    : "=l"(d) : "l"(a), "l"(b))
#define F2FMA(d,a,b,c) asm("fma.rn.f32x2 %0,%1,%2,%3;" : "=l"(d) : "l"(a), "l"(b), "l"(c))

// ---------------------------------------------------------------------------
// Kernel 1: proj GEMM, 64x64 tiles (grid 32x8 = 256 blocks), 256 threads.
// Thread owns 4 rows x 4 cols = 16 acc (~56 regs) -> multiple blocks/SM.
// Combined output [hi|hj] is (BN) x 512. K chunked at 32.
// ---------------------------------------------------------------------------
#define KC 32
__global__ __launch_bounds__(256) void proj_kernel(
    const float* __restrict__ slots, const float* __restrict__ W_m1,
    const float* __restrict__ b_m1)
{
    const int r0   = blockIdx.x * 64;        // row-block base (b*N + n)
    const int part = blockIdx.y >> 2;        // 0 -> hi, 1 -> hj
    const int c0   = (blockIdx.y & 3) * 64;  // column base within 256-wide half
    const int tid  = threadIdx.x;
    const int ty   = tid >> 4, tx = tid & 15;

    __shared__ float As[64][KC + 1];         // pad -> conflict-free col reads
    __shared__ float Ws[KC][65];

    float acc[4][4];
#pragma unroll
    for (int r = 0; r < 4; ++r)
#pragma unroll
        for (int c = 0; c < 4; ++c) acc[r][c] = 0.f;

    const float* wsrc = W_m1 + (size_t)(part * D) * H + c0;

    for (int kc = 0; kc < D; kc += KC) {
        // A chunk: 64 x 32 = 2048 elems, 8 per thread, coalesced 32-wide rows
#pragma unroll
        for (int l = 0; l < 8; ++l) {
            const int idx = tid + l * 256;
            const int r = idx >> 5, k = idx & 31;
            As[r][k] = slots[(r0 + r) * D + kc + k];
        }
        // W chunk: 32 x 64 = 2048 elems, 8 per thread, coalesced 64-wide rows
#pragma unroll
        for (int l = 0; l < 8; ++l) {
            const int idx = tid + l * 256;
            const int k = idx >> 6, c = idx & 63;
            Ws[k][c] = wsrc[(kc + k) * H + c];
        }
        __syncthreads();

#pragma unroll
        for (int k = 0; k < KC; ++k) {
            float wv[4], av[4];
#pragma unroll
            for (int c = 0; c < 4; ++c) wv[c] = Ws[k][tx + 16 * c];
#pragma unroll
            for (int r = 0; r < 4; ++r) av[r] = As[ty + 16 * r][k];
#pragma unroll
            for (int r = 0; r < 4; ++r)
#pragma unroll
                for (int c = 0; c < 4; ++c)
                    acc[r][c] = fmaf(av[r], wv[c], acc[r][c]);
        }
        __syncthreads();
    }

    if (part == 0) {
#pragma unroll
        for (int r = 0; r < 4; ++r)
#pragma unroll
            for (int c = 0; c < 4; ++c)
                g_hi[(size_t)(r0 + ty + 16 * r) * H + c0 + tx + 16 * c] = acc[r][c];
    } else {
        float bm[4];
#pragma unroll
        for (int c = 0; c < 4; ++c) bm[c] = b_m1[c0 + tx + 16 * c];
#pragma unroll
        for (int r = 0; r < 4; ++r)
#pragma unroll
            for (int c = 0; c < 4; ++c)
                g_hj[(size_t)(r0 + ty + 16 * r) * H + c0 + tx + 16 * c] = acc[r][c] + bm[c];
    }
}

// ---------------------------------------------------------------------------
// Kernel 2 (dominant): G[b,i,h] = sum_j a[b,i,j] * gelu(hi[b,i,h] + hjp[b,j,h])
// 2 i-rows per block (grid 1024), 128 threads, thread owns an h-pair (f32x2).
// gelu via A&S 7.1.28 with 1/sqrt2 folded into coefficients, and the
// reciprocal 16th power computed on the MUFU pipe:
//   P = 1 + b1'|x| + ... + b6'|x|^6
//   P^-16 = ex2(-16 * lg2(P))          <- 2 MUFU + 2 FMUL-imm, no squarings
//   gelu(x) = 0.5*((x+|x|) - |x| * P^-16)
// ---------------------------------------------------------------------------
__global__ __launch_bounds__(128) void msg_agg_kernel(
    const float* __restrict__ adj)
{
    const int row0 = blockIdx.x * 2;        // global row = b*N + i
    const int b    = row0 >> 8;
    const int i0   = row0 & (N - 1);
    const int tid  = threadIdx.x;           // h-pair = (2*tid, 2*tid+1)

    __shared__ ull a2_s[2][N];              // packed {0.5a, 0.5a}
    const float* adj_b = adj + ((size_t)b * N + i0) * N;
#pragma unroll
    for (int idx = tid; idx < 2 * N; idx += 128) {
        const float av = 0.5f * adj_b[idx];
        ((ull*)a2_s)[idx] = pack2(av);
    }
    __syncthreads();

    const ull ABSM = 0x7fffffff7fffffffULL;
    const ull SGNM = 0x8000000080000000ULL;
    const ull cone = pack2(1.0f);
    const ull cb1  = pack2(4.98677908e-2f);  // b1 * 2^-1/2
    const ull cb2  = pack2(2.11410062e-2f);  // b2 * 2^-1
    const ull cb3  = pack2(3.27762714e-3f);  // b3 * 2^-3/2
    const ull cb4  = pack2(3.80035750e-5f);  // b4 * 2^-2
    const ull cb5  = pack2(4.88897213e-5f);  // b5 * 2^-5/2
    const ull cb6  = pack2(5.38297500e-6f);  // b6 * 2^-3

    const ull* hj2 = (const ull*)(g_hj + (size_t)b * N * H) + tid;
    ull hi2[2];
    hi2[0] = ((const ull*)(g_hi + (size_t) row0      * H))[tid];
    hi2[1] = ((const ull*)(g_hi + (size_t)(row0 + 1) * H))[tid];

    ull acc[2] = {0ULL, 0ULL};              // packed {0.f,0.f}

#pragma unroll 8
    for (int j = 0; j < N; ++j) {
        const ull hjv = hj2[(size_t)j * (H / 2)];
#pragma unroll
        for (int r = 0; r < 2; ++r) {
            ull x; F2ADD(x, hi2[r], hjv);
            const ull ax = x & ABSM;
            ull p;
            F2FMA(p, cb6, ax, cb5);
            F2FMA(p, p, ax, cb4);
            F2FMA(p, p, ax, cb3);
            F2FMA(p, p, ax, cb2);
            F2FMA(p, p, ax, cb1);
            F2FMA(p, p, ax, cone);          // P
            float plo, phi, llo, lhi, elo, ehi;
            asm("mov.b64 {%0,%1},%2;" : "=f"(plo), "=f"(phi) : "l"(p));
            asm("lg2.approx.f32 %0,%1;" : "=f"(llo) : "f"(plo));
            asm("lg2.approx.f32 %0,%1;" : "=f"(lhi) : "f"(phi));
            llo *= -16.0f;                  // FMUL-imm, rt=1
            lhi *= -16.0f;
            asm("ex2.approx.f32 %0,%1;" : "=f"(elo) : "f"(llo));
            asm("ex2.approx.f32 %0,%1;" : "=f"(ehi) : "f"(lhi));
            ull e; asm("mov.b64 %0,{%1,%2};" : "=l"(e) : "f"(elo), "f"(ehi));
            ull u; F2ADD(u, x, ax);         // x + |x|
            const ull nax = ax ^ SGNM;      // -|x|
            ull g2; F2FMA(g2, nax, e, u);   // 2*gelu(x)
            F2FMA(acc[r], a2_s[r][j], g2, acc[r]);
        }
    }

    ((ull*)(g_G + (size_t) row0      * H))[tid] = acc[0];
    ((ull*)(g_G + (size_t)(row0 + 1) * H))[tid] = acc[1];
}

// ---------------------------------------------------------------------------
// Kernel 3: fused epilogue. 8 rows per block, 512 threads (grid 256).
//   agg = G @ W_m2 + rowsum(a)*b_m2
//   u   = slots@W_u1[:D] + agg@W_u1[D:] + b_u1 ; LayerNorm ; gelu
//   out = slots + u @ W_u2 + b_u2
// ---------------------------------------------------------------------------
__global__ __launch_bounds__(512) void epilogue_kernel(
    const float* __restrict__ slots, const float* __restrict__ adj,
    const float* __restrict__ W_m2, const float* __restrict__ b_m2,
    const float* __restrict__ W_u1, const float* __restrict__ b_u1,
    const float* __restrict__ ln_g, const float* __restrict__ ln_b,
    const float* __restrict__ W_u2, const float* __restrict__ b_u2,
    float* __restrict__ out)
{
    const int R  = 8;
    const int r0 = blockIdx.x * R;          // global row = b*N + n
    const int b  = r0 >> 8;
    const int n0 = r0 & (N - 1);
    const int tid = threadIdx.x;
    const int warp = tid >> 5, lane = tid & 31;

    __shared__ float buf_s[R][H];           // G tile, later reused as u tile
    __shared__ float s_s [R][D];
    __shared__ float agg_s[R][D];
    __shared__ float asum_s[R];
    __shared__ float mu_s[R], rstd_s[R];

    for (int idx = tid; idx < R * H; idx += 512)
        ((float*)buf_s)[idx] = g_G[r0 * H + idx];
    for (int idx = tid; idx < R * D; idx += 512)
        ((float*)s_s)[idx] = slots[r0 * D + idx];

    // adjacency row sums: warps 0..7 handle rows 0..7
    if (warp < R) {
        const float* arow = adj + ((size_t)b * N + n0 + warp) * N;
        float s = 0.f;
#pragma unroll
        for (int k = 0; k < 8; ++k) s += arow[lane + k * 32];
#pragma unroll
        for (int o = 16; o > 0; o >>= 1) s += __shfl_xor_sync(~0u, s, o);
        if (lane == 0) asum_s[warp] = s;
    }
    __syncthreads();

    // aggregated = G @ W_m2 + asum * b_m2
    {
        const int d  = tid & (D - 1);
        const int rb = (tid >> 7) * 2;       // rows rb, rb+1
        float acc[2];
        const float bm2 = b_m2[d];
#pragma unroll
        for (int r = 0; r < 2; ++r) acc[r] = asum_s[rb + r] * bm2;
#pragma unroll 8
        for (int hh = 0; hh < H; ++hh) {
            const float w = W_m2[hh * D + d];
#pragma unroll
            for (int r = 0; r < 2; ++r)
                acc[r] = fmaf(buf_s[rb + r][hh], w, acc[r]);
        }
        __syncthreads();                     // all reads of buf_s-as-G done
#pragma unroll
        for (int r = 0; r < 2; ++r) agg_s[rb + r][d] = acc[r];
    }
    __syncthreads();

    // u = slots@W_u1[:D] + agg@W_u1[D:] + b_u1   (overwrite buf_s)
    {
        const int h  = tid & 255;
        const int g  = tid >> 8;             // 0,1 -> rows 4g..4g+3
        float acc[4];
        const float bu = b_u1[h];
#pragma unroll
        for (int r = 0; r < 4; ++r) acc[r] = bu;
#pragma unroll 8
        for (int d = 0; d < D; ++d) {
            const float w1 = W_u1[d * H + h];
            const float w2 = W_u1[(D + d) * H + h];
#pragma unroll
            for (int r = 0; r < 4; ++r) {
                acc[r] = fmaf(s_s[4 * g + r][d], w1, acc[r]);
                acc[r] = fmaf(agg_s[4 * g + r][d], w2, acc[r]);
            }
        }
#pragma unroll
        for (int r = 0; r < 4; ++r) buf_s[4 * g + r][h] = acc[r];
    }
    __syncthreads();

    // LayerNorm stats: warps 0..7, one row each (two-pass)
    if (warp < R) {
        const int r = warp;
        float s = 0.f;
#pragma unroll
        for (int k = 0; k < 8; ++k) s += buf_s[r][lane + k * 32];
#pragma unroll
        for (int o = 16; o > 0; o >>= 1) s += __shfl_xor_sync(~0u, s, o);
        const float mu = s * (1.f / H);
        float ss = 0.f;
#pragma unroll
        for (int k = 0; k < 8; ++k) {
            const float v = buf_s[r][lane + k * 32] - mu;
            ss += v * v;
        }
#pragma unroll
        for (int o = 16; o > 0; o >>= 1) ss += __shfl_xor_sync(~0u, ss, o);
        if (lane == 0) {
            mu_s[r]   = mu;
            rstd_s[r] = rsqrtf(ss * (1.f / H) + 1e-5f);
        }
    }
    __syncthreads();

    // normalize + gelu (in place)
    {
        const int h = tid & 255;
        const int g = tid >> 8;
        const float gg = ln_g[h], bb = ln_b[h];
#pragma unroll
        for (int r = 0; r < 4; ++r) {
            const int rr = 4 * g + r;
            const float v = (buf_s[rr][h] - mu_s[rr]) * rstd_s[rr] * gg + bb;
            buf_s[rr][h] = gelu_exact(v);
        }
    }
    __syncthreads();

    // out = slots + u @ W_u2 + b_u2
    {
        const int d  = tid & (D - 1);
        const int rb = (tid >> 7) * 2;
        float acc[2];
        const float bu2 = b_u2[d];
#pragma unroll
        for (int r = 0; r < 2; ++r) acc[r] = bu2;
#pragma unroll 8
        for (int hh = 0; hh < H; ++hh) {
            const float w = W_u2[hh * D + d];
#pragma unroll
            for (int r = 0; r < 2; ++r)
                acc[r] = fmaf(buf_s[rb + r][hh], w, acc[r]);
        }
#pragma unroll
        for (int r = 0; r < 2; ++r)
            out[(r0 + rb + r) * D + d] = s_s[rb + r][d] + acc[r];
    }
}

// ---------------------------------------------------------------------------
extern "C" void kernel_launch(void* const* d_in, const int* in_sizes, int n_in,
                              void* d_out, int out_size)
{
    const float* slots = (const float*)d_in[0];
    const float* adj   = (const float*)d_in[1];
    const float* W_m1  = (const float*)d_in[2];
    const float* b_m1  = (const float*)d_in[3];
    const float* W_m2  = (const float*)d_in[4];
    const float* b_m2  = (const float*)d_in[5];
    const float* W_u1  = (const float*)d_in[6];
    const float* b_u1  = (const float*)d_in[7];
    const float* ln_g  = (const float*)d_in[8];
    const float* ln_b  = (const float*)d_in[9];
    const float* W_u2  = (const float*)d_in[10];
    const float* b_u2  = (const float*)d_in[11];
    float* out = (float*)d_out;

    dim3 pg(BN / 64, 8);
    proj_kernel<<<pg, 256>>>(slots, W_m1, b_m1);
    msg_agg_kernel<<<BN / 2, 128>>>(adj);
    epilogue_kernel<<<BN / 8, 512>>>(slots, adj, W_m2, b_m2, W_u1, b_u1,
                                     ln_g, ln_b, W_u2, b_u2, out);
}